// round 16
// baseline (speedup 1.0000x reference)
#include <cuda_runtime.h>
#include <cuda_bf16.h>
#include <math.h>
#include <stdint.h>

#define Bz 64
#define Tt 512
#define Dd 1024
#define Hh 1024
#define G4 4096

__device__ float g_xz[(size_t)Tt * Bz * G4];
__device__ float g_hs0[(size_t)Tt * Bz * Hh];
__device__ uint32_t g_hP[2][2][512][64];       // [par][hi/lo][k2][b] bf16x2 words
__device__ uint4 g_Upk[1048576];               // 16 MB packed bf16 hi/lo U frags

// hierarchical barrier state (all return to 0 after each launch: 512 flips, even)
__device__ unsigned g_cnt_sub[8];
__device__ unsigned g_cnt_master = 0;
__device__ unsigned g_flags[128 * 8];          // one padded flag word per block

// Grid barrier: atomic-everything semantics (proven correct R8/R11/R13/R14),
// but contention-free: hierarchical arrivals + per-block flag broadcast.
__device__ __forceinline__ void grid_sync(unsigned& sense, int blk) {
    __threadfence();
    __syncthreads();
    if (threadIdx.x == 0) {
        const unsigned s = sense ^ 1u;
        sense = s;
        bool is_releaser = false;
        if (atomicAdd(&g_cnt_sub[blk & 7], 1u) == 15u) {
            if (atomicAdd(&g_cnt_master, 1u) == 7u) {
                is_releaser = true;
#pragma unroll
                for (int i = 0; i < 8; i++) atomicExch(&g_cnt_sub[i], 0u);
                atomicExch(&g_cnt_master, 0u);
                __threadfence();
                for (int i = 0; i < 128; i++) atomicExch(&g_flags[i * 8], s);
            }
        }
        if (!is_releaser) {
            while (atomicAdd(&g_flags[blk * 8], 0u) != s) { __nanosleep(64); }
        }
    }
    __syncthreads();
}

__device__ __forceinline__ void split_tf32(float x, uint32_t& hi, uint32_t& lo) {
    uint32_t h;
    asm("cvt.rna.tf32.f32 %0, %1;" : "=r"(h) : "f"(x));
    const float hf = __uint_as_float(h);
    const float lf = x - hf;
    uint32_t l;
    asm("cvt.rna.tf32.f32 %0, %1;" : "=r"(l) : "f"(lf));
    hi = h; lo = l;
}

__device__ __forceinline__ void mma_tf32(float* c, const uint32_t* a, const uint32_t* b) {
    asm volatile(
        "mma.sync.aligned.m16n8k8.row.col.f32.tf32.tf32.f32 "
        "{%0,%1,%2,%3}, {%4,%5,%6,%7}, {%8,%9}, {%0,%1,%2,%3};"
        : "+f"(c[0]), "+f"(c[1]), "+f"(c[2]), "+f"(c[3])
        : "r"(a[0]), "r"(a[1]), "r"(a[2]), "r"(a[3]), "r"(b[0]), "r"(b[1]));
}

__device__ __forceinline__ void mma_bf16(float* c, const uint32_t* a, const uint32_t* b) {
    asm volatile(
        "mma.sync.aligned.m16n8k16.row.col.f32.bf16.bf16.f32 "
        "{%0,%1,%2,%3}, {%4,%5,%6,%7}, {%8,%9}, {%0,%1,%2,%3};"
        : "+f"(c[0]), "+f"(c[1]), "+f"(c[2]), "+f"(c[3])
        : "r"(a[0]), "r"(a[1]), "r"(a[2]), "r"(a[3]), "r"(b[0]), "r"(b[1]));
}

__device__ __forceinline__ uint32_t b2bits(__nv_bfloat162 v) {
    return *reinterpret_cast<uint32_t*>(&v);
}

__device__ __forceinline__ void cp16(void* dst_smem, const void* src) {
    uint32_t d = (uint32_t)__cvta_generic_to_shared(dst_smem);
    asm volatile("cp.async.cg.shared.global [%0], [%1], 16;" :: "r"(d), "l"(src));
}
#define CP_COMMIT() asm volatile("cp.async.commit_group;")
#define CP_WAIT0()  asm volatile("cp.async.wait_group 0;")

// ---------------------------------------------------------------------------
// GEMM (R11/R13/R14 verbatim, proven)
// ---------------------------------------------------------------------------
#define APAD 20
#define WPAD 136

__global__ void __launch_bounds__(256) gemm_xz_kernel(
    const float* __restrict__ Aext, const float* __restrict__ W,
    const float* __restrict__ bias, int layer0)
{
    __shared__ __align__(16) float As[2][128][APAD];
    __shared__ __align__(16) float Ws[2][16][WPAD];

    const int tid = threadIdx.x;
    const int bm = blockIdx.y * 128;
    const int bn = blockIdx.x * 128;

    const int wid = tid >> 5;
    const int lane = tid & 31;
    const int wm = wid >> 2;
    const int wn = wid & 3;
    const int gid = lane >> 2;
    const int tig = lane & 3;

    const int aRow = tid >> 1;
    const int aOff = (tid & 1) << 3;
    const float* aptr;
    {
        const int m = bm + aRow;
        if (layer0) aptr = Aext + ((size_t)(m & 63) * Tt + (m >> 6)) * Dd;
        else        aptr = g_hs0 + (size_t)m * Hh;
    }
    const int wRow = tid >> 4;
    const int wOff = (tid & 15) << 3;
    const float* wptr = W + (size_t)wRow * G4 + bn + wOff;

    cp16(&As[0][aRow][aOff],     aptr + aOff);
    cp16(&As[0][aRow][aOff + 4], aptr + aOff + 4);
    cp16(&Ws[0][wRow][wOff],     wptr);
    cp16(&Ws[0][wRow][wOff + 4], wptr + 4);
    CP_COMMIT();

    float acc[4][4][4];
#pragma unroll
    for (int i = 0; i < 4; i++)
#pragma unroll
        for (int j = 0; j < 4; j++)
#pragma unroll
            for (int q = 0; q < 4; q++) acc[i][j][q] = 0.0f;

    for (int k0 = 0; k0 < 1024; k0 += 16) {
        CP_WAIT0();
        __syncthreads();
        const int buf = (k0 >> 4) & 1;
        if (k0 + 16 < 1024) {
            const int nb = buf ^ 1;
            const float* an = aptr + k0 + 16;
            const float* wn_ = wptr + (size_t)(k0 + 16) * G4;
            cp16(&As[nb][aRow][aOff],     an + aOff);
            cp16(&As[nb][aRow][aOff + 4], an + aOff + 4);
            cp16(&Ws[nb][wRow][wOff],     wn_);
            cp16(&Ws[nb][wRow][wOff + 4], wn_ + 4);
            CP_COMMIT();
        }
#pragma unroll
        for (int s = 0; s < 2; s++) {
            const int ks = s * 8;
            uint32_t a_hi[4][4], a_lo[4][4], b_hi[4][2], b_lo[4][2];
#pragma unroll
            for (int mt = 0; mt < 4; mt++) {
                const int m = wm * 64 + mt * 16 + gid;
                split_tf32(As[buf][m][ks + tig],         a_hi[mt][0], a_lo[mt][0]);
                split_tf32(As[buf][m + 8][ks + tig],     a_hi[mt][1], a_lo[mt][1]);
                split_tf32(As[buf][m][ks + tig + 4],     a_hi[mt][2], a_lo[mt][2]);
                split_tf32(As[buf][m + 8][ks + tig + 4], a_hi[mt][3], a_lo[mt][3]);
            }
#pragma unroll
            for (int nt = 0; nt < 4; nt++) {
                const int n = wn * 32 + nt * 8 + gid;
                split_tf32(Ws[buf][ks + tig][n],     b_hi[nt][0], b_lo[nt][0]);
                split_tf32(Ws[buf][ks + tig + 4][n], b_hi[nt][1], b_lo[nt][1]);
            }
#pragma unroll
            for (int mt = 0; mt < 4; mt++)
#pragma unroll
                for (int nt = 0; nt < 4; nt++) {
                    mma_tf32(acc[mt][nt], a_hi[mt], b_hi[nt]);
                    mma_tf32(acc[mt][nt], a_hi[mt], b_lo[nt]);
                    mma_tf32(acc[mt][nt], a_lo[mt], b_hi[nt]);
                }
        }
    }

#pragma unroll
    for (int mt = 0; mt < 4; mt++) {
#pragma unroll
        for (int nt = 0; nt < 4; nt++) {
            const int gn = bn + wn * 32 + nt * 8 + 2 * tig;
            const float b0v = bias[gn];
            const float b1v = bias[gn + 1];
            const int r0 = bm + wm * 64 + mt * 16 + gid;
            float* p0 = g_xz + (size_t)r0 * G4 + gn;
            float* p1 = g_xz + (size_t)(r0 + 8) * G4 + gn;
            p0[0] = acc[mt][nt][0] + b0v;
            p0[1] = acc[mt][nt][1] + b1v;
            p1[0] = acc[mt][nt][2] + b0v;
            p1[1] = acc[mt][nt][3] + b1v;
        }
    }
}

// ---------------------------------------------------------------------------
// U prep: bf16 hi/lo, m16n8k16 B-frag order (R14 verbatim, proven)
// ---------------------------------------------------------------------------
__global__ void __launch_bounds__(256) prep_upk_kernel(const float* __restrict__ U) {
    const int i = blockIdx.x * 256 + threadIdx.x;   // 0..1048575
    const int lane = i & 31;
    const int nt   = (i >> 5) & 3;
    const int ks   = (i >> 7) & 31;
    const int kw   = (i >> 12) & 1;
    const int blk  = i >> 13;
    const int tig = lane & 3;
    const int gid = lane >> 2;
    const int kA = kw * 512 + ks * 16 + 2 * tig;
    const int col = nt * Hh + blk * 8 + gid;

    const float u00 = U[(size_t)kA * G4 + col];
    const float u01 = U[(size_t)(kA + 1) * G4 + col];
    const float u10 = U[(size_t)(kA + 8) * G4 + col];
    const float u11 = U[(size_t)(kA + 9) * G4 + col];

    __nv_bfloat162 h0 = __floats2bfloat162_rn(u00, u01);
    __nv_bfloat162 h1 = __floats2bfloat162_rn(u10, u11);
    __nv_bfloat162 l0 = __floats2bfloat162_rn(u00 - __bfloat162float(h0.x),
                                              u01 - __bfloat162float(h0.y));
    __nv_bfloat162 l1 = __floats2bfloat162_rn(u10 - __bfloat162float(h1.x),
                                              u11 - __bfloat162float(h1.y));
    uint4 v;
    v.x = b2bits(h0); v.y = b2bits(h1); v.z = b2bits(l0); v.w = b2bits(l1);
    g_Upk[i] = v;
}

// ---------------------------------------------------------------------------
// Persistent bf16 scan (R14 verbatim except the barrier call signature)
// ---------------------------------------------------------------------------
#define SCAN_SMEM (131072 + 73728 + 8192)   // 212992 B

__global__ void __launch_bounds__(256, 1) lstm_scan_tc(
    const int* __restrict__ lengths, float* __restrict__ out_base,
    float* __restrict__ out_tail, int layer)
{
    extern __shared__ uint8_t smraw[];
    uint4* usm = (uint4*)smraw;                          // [kw][ks32][nt4][lane32]
    uint32_t* hsm = (uint32_t*)(smraw + 131072);         // [kw][stage2][hl2][32][72]
    float* red = (float*)(smraw + 131072 + 73728);       // [16][128]

    const int tid = threadIdx.x;
    const int blk = blockIdx.x;
    const int wid = tid >> 5;
    const int lane = tid & 31;
    const int gid = lane >> 2;
    const int tig = lane & 3;
    const int kw = tid >> 7;
    const int gtid = tid & 127;
    const int w4 = wid & 3;
    const int j0 = blk * 8;
    unsigned sense = 0;

    // U resident fill: 64 KB per group (once)
    {
        const uint4* usrc = g_Upk + ((size_t)(blk * 2 + kw)) * 4096 + gtid * 32;
        uint4* udst = usm + kw * 4096 + gtid * 32;
#pragma unroll
        for (int q = 0; q < 32; q++) cp16(udst + q, usrc + q);
    }
    CP_COMMIT();

    // zero initial h (parity 0, hi+lo)
    {
        uint2* p = reinterpret_cast<uint2*>(&g_hP[0][0][0][0]);
        __stcg(p + (blk * 256 + tid), make_uint2(0u, 0u));
    }

    const int b0 = w4 * 16 + gid;
    const int b1 = b0 + 8;
    const int jA = j0 + 2 * tig;
    const int k2g = blk * 4 + tig;
    int len0 = 0, len1 = 0;
    if (kw == 0) { len0 = lengths[b0]; len1 = lengths[b1]; }

    float cb[4] = {0.f, 0.f, 0.f, 0.f};
    float hp[4] = {0.f, 0.f, 0.f, 0.f};

    grid_sync(sense, blk);   // sync #1

    const int prow = gtid >> 1;
    const int phl = prow >> 5;
    const int pr  = prow & 31;
    const int pcol = (gtid & 1) * 32;
    uint32_t* hgrp = hsm + kw * 9216;

    for (int t = 0; t < Tt; t++) {
        const float* xz = g_xz + (size_t)t * (Bz * G4);
        float2 xv[4][2];
        if (kw == 0) {
#pragma unroll
            for (int g = 0; g < 4; g++) {
                xv[g][0] = *(const float2*)(xz + (size_t)b0 * G4 + g * Hh + jA);
                xv[g][1] = *(const float2*)(xz + (size_t)b1 * G4 + g * Hh + jA);
            }
        }
        if (t) grid_sync(sense, blk);
        const int par = t & 1;

        float accA[4][4], accB[4][4], accC[4][4];
#pragma unroll
        for (int nt = 0; nt < 4; nt++)
#pragma unroll
            for (int q = 0; q < 4; q++) {
                accA[nt][q] = 0.f; accB[nt][q] = 0.f; accC[nt][q] = 0.f;
            }

        // prefetch chunk 0
        {
            const uint32_t* hsrc = &g_hP[par][phl][kw * 256 + pr][0] + pcol;
            uint32_t* hdst = hgrp + phl * 2304 + pr * 72 + pcol;
#pragma unroll
            for (int q = 0; q < 8; q++) cp16(hdst + q * 4, hsrc + q * 4);
        }
        CP_COMMIT();

        for (int c = 0; c < 8; c++) {
            const int s = c & 1;
            CP_WAIT0();
            __syncthreads();
            if (c < 7) {
                const uint32_t* hsrc = &g_hP[par][phl][kw * 256 + (c + 1) * 32 + pr][0] + pcol;
                uint32_t* hdst = hgrp + (s ^ 1) * 4608 + phl * 2304 + pr * 72 + pcol;
#pragma unroll
                for (int q = 0; q < 8; q++) cp16(hdst + q * 4, hsrc + q * 4);
                CP_COMMIT();
            }
            const uint32_t* Hhi = hgrp + s * 4608;
            const uint32_t* Hlo = Hhi + 2304;
            const uint4* Ug = usm + kw * 4096;
#pragma unroll
            for (int sk = 0; sk < 4; sk++) {
                const int r0 = sk * 8 + tig;
                const int r1 = r0 + 4;
                uint32_t ah[4], al[4];
                ah[0] = Hhi[r0 * 72 + b0]; ah[1] = Hhi[r0 * 72 + b1];
                ah[2] = Hhi[r1 * 72 + b0]; ah[3] = Hhi[r1 * 72 + b1];
                al[0] = Hlo[r0 * 72 + b0]; al[1] = Hlo[r0 * 72 + b1];
                al[2] = Hlo[r1 * 72 + b0]; al[3] = Hlo[r1 * 72 + b1];
                const int ksg = c * 4 + sk;
#pragma unroll
                for (int nt = 0; nt < 4; nt++) {
                    const uint4 v = Ug[(ksg * 4 + nt) * 32 + lane];
                    uint32_t bh[2], bl[2];
                    bh[0] = v.x; bh[1] = v.y; bl[0] = v.z; bl[1] = v.w;
                    mma_bf16(accA[nt], ah, bh);
                    mma_bf16(accB[nt], ah, bl);
                    mma_bf16(accC[nt], al, bh);
                }
            }
        }
        __syncthreads();

        if (kw == 1) {
#pragma unroll
            for (int nt = 0; nt < 4; nt++)
#pragma unroll
                for (int q = 0; q < 4; q++)
                    red[(nt * 4 + q) * 128 + w4 * 32 + lane] =
                        accA[nt][q] + accB[nt][q] + accC[nt][q];
        }
        __syncthreads();

        if (kw == 0) {
            float h2a[4];
#pragma unroll
            for (int q = 0; q < 4; q++) {
                const int r = q >> 1;
                const int ccsel = q & 1;
                const float zi = accA[0][q] + accB[0][q] + accC[0][q]
                               + red[(0 * 4 + q) * 128 + w4 * 32 + lane]
                               + (ccsel ? xv[0][r].y : xv[0][r].x);
                const float zf = accA[1][q] + accB[1][q] + accC[1][q]
                               + red[(1 * 4 + q) * 128 + w4 * 32 + lane]
                               + (ccsel ? xv[1][r].y : xv[1][r].x);
                const float zg = accA[2][q] + accB[2][q] + accC[2][q]
                               + red[(2 * 4 + q) * 128 + w4 * 32 + lane]
                               + (ccsel ? xv[2][r].y : xv[2][r].x);
                const float zo = accA[3][q] + accB[3][q] + accC[3][q]
                               + red[(3 * 4 + q) * 128 + w4 * 32 + lane]
                               + (ccsel ? xv[3][r].y : xv[3][r].x);

                const float ig = 1.0f / (1.0f + __expf(-zi));
                const float fg = 1.0f / (1.0f + __expf(-zf));
                const float gg = tanhf(zg);
                const float og = 1.0f / (1.0f + __expf(-zo));

                const float cn = fg * cb[q] + ig * gg;
                const float hn = og * tanhf(cn);

                const bool msk = t < (r ? len1 : len0);
                const float h2 = msk ? hn : hp[q];
                const float c2 = msk ? cn : cb[q];
                hp[q] = h2; cb[q] = c2;
                h2a[q] = h2;

                const int b = r ? b1 : b0;
                const int j = jA + ccsel;
                if (layer == 0) {
                    g_hs0[(size_t)t * (Bz * Hh) + (size_t)b * Hh + j] = h2;
                } else {
                    out_base[(size_t)b * ((size_t)Tt * Hh) + (size_t)t * Hh + j] = h2;
                }
            }
            {
                __nv_bfloat162 vh = __floats2bfloat162_rn(h2a[0], h2a[1]);
                __nv_bfloat162 vl = __floats2bfloat162_rn(
                    h2a[0] - __bfloat162float(vh.x), h2a[1] - __bfloat162float(vh.y));
                __stcg(&g_hP[par ^ 1][0][k2g][b0], b2bits(vh));
                __stcg(&g_hP[par ^ 1][1][k2g][b0], b2bits(vl));
            }
            {
                __nv_bfloat162 vh = __floats2bfloat162_rn(h2a[2], h2a[3]);
                __nv_bfloat162 vl = __floats2bfloat162_rn(
                    h2a[2] - __bfloat162float(vh.x), h2a[3] - __bfloat162float(vh.y));
                __stcg(&g_hP[par ^ 1][0][k2g][b1], b2bits(vh));
                __stcg(&g_hP[par ^ 1][1][k2g][b1], b2bits(vl));
            }
        }
    }

    if (layer && kw == 0) {
#pragma unroll
        for (int q = 0; q < 4; q++) {
            const int b = (q >> 1) ? b1 : b0;
            const int j = jA + (q & 1);
            out_tail[(size_t)b * Hh + j] = hp[q];
            out_tail[(size_t)Bz * Hh + (size_t)b * Hh + j] = cb[q];
        }
    }
}

extern "C" void kernel_launch(void* const* d_in, const int* in_sizes, int n_in,
                              void* d_out, int out_size) {
    (void)in_sizes; (void)n_in; (void)out_size;
    const float* x  = (const float*)d_in[0];
    const int* lens = (const int*)d_in[1];
    const float* W0 = (const float*)d_in[2];
    const float* U0 = (const float*)d_in[3];
    const float* b0 = (const float*)d_in[4];
    const float* W1 = (const float*)d_in[5];
    const float* U1 = (const float*)d_in[6];
    const float* b1 = (const float*)d_in[7];
    float* out = (float*)d_out;

    cudaFuncSetAttribute(lstm_scan_tc,
                         cudaFuncAttributeMaxDynamicSharedMemorySize, SCAN_SMEM);

    const dim3 ggrid(G4 / 128, (Tt * Bz) / 128);

    gemm_xz_kernel<<<ggrid, 256>>>(x, W0, b0, 1);
    prep_upk_kernel<<<4096, 256>>>(U0);
    lstm_scan_tc<<<128, 256, SCAN_SMEM>>>(lens, nullptr, nullptr, 0);

    gemm_xz_kernel<<<ggrid, 256>>>(nullptr, W1, b1, 0);
    prep_upk_kernel<<<4096, 256>>>(U1);
    float* tail = out + (size_t)Bz * Tt * Hh;
    lstm_scan_tc<<<128, 256, SCAN_SMEM>>>(lens, out, tail, 1);
}

// round 17
// speedup vs baseline: 1.1610x; 1.1610x over previous
#include <cuda_runtime.h>
#include <cuda_bf16.h>
#include <math.h>
#include <stdint.h>

#define Bz 64
#define Tt 512
#define Dd 1024
#define Hh 1024
#define G4 4096

__device__ float g_xz[(size_t)Tt * Bz * G4];
__device__ float g_hs0[(size_t)Tt * Bz * Hh];
__device__ uint32_t g_hP[2][2][512][64];       // [par][hi/lo][k2][b] bf16x2 words
__device__ uint4 g_Upk[1048576];               // 16 MB packed bf16 hi/lo U frags

__device__ unsigned g_bar_count = 0;
__device__ unsigned g_bar_sense = 0;

// flat sense-reversing barrier, atomic-poll (R14-proven fastest correct variant)
__device__ __forceinline__ void grid_sync(unsigned& sense, unsigned nblocks) {
    __threadfence();
    __syncthreads();
    if (threadIdx.x == 0) {
        const unsigned s = sense ^ 1u;
        sense = s;
        if (atomicAdd(&g_bar_count, 1u) == nblocks - 1u) {
            atomicExch(&g_bar_count, 0u);
            __threadfence();
            atomicExch(&g_bar_sense, s);
        } else {
            while (atomicAdd(&g_bar_sense, 0u) != s) { __nanosleep(64); }
        }
    }
    __syncthreads();
}

__device__ __forceinline__ void split_tf32(float x, uint32_t& hi, uint32_t& lo) {
    uint32_t h;
    asm("cvt.rna.tf32.f32 %0, %1;" : "=r"(h) : "f"(x));
    const float hf = __uint_as_float(h);
    const float lf = x - hf;
    uint32_t l;
    asm("cvt.rna.tf32.f32 %0, %1;" : "=r"(l) : "f"(lf));
    hi = h; lo = l;
}

__device__ __forceinline__ void mma_tf32(float* c, const uint32_t* a, const uint32_t* b) {
    asm volatile(
        "mma.sync.aligned.m16n8k8.row.col.f32.tf32.tf32.f32 "
        "{%0,%1,%2,%3}, {%4,%5,%6,%7}, {%8,%9}, {%0,%1,%2,%3};"
        : "+f"(c[0]), "+f"(c[1]), "+f"(c[2]), "+f"(c[3])
        : "r"(a[0]), "r"(a[1]), "r"(a[2]), "r"(a[3]), "r"(b[0]), "r"(b[1]));
}

__device__ __forceinline__ void mma_bf16(float* c, const uint32_t* a, const uint32_t* b) {
    asm volatile(
        "mma.sync.aligned.m16n8k16.row.col.f32.bf16.bf16.f32 "
        "{%0,%1,%2,%3}, {%4,%5,%6,%7}, {%8,%9}, {%0,%1,%2,%3};"
        : "+f"(c[0]), "+f"(c[1]), "+f"(c[2]), "+f"(c[3])
        : "r"(a[0]), "r"(a[1]), "r"(a[2]), "r"(a[3]), "r"(b[0]), "r"(b[1]));
}

__device__ __forceinline__ uint32_t b2bits(__nv_bfloat162 v) {
    return *reinterpret_cast<uint32_t*>(&v);
}

__device__ __forceinline__ uint32_t ldcg_u32(const uint32_t* p) {
    uint32_t v;
    asm volatile("ld.global.cg.u32 %0, [%1];" : "=r"(v) : "l"(p));
    return v;
}

__device__ __forceinline__ void cp16(void* dst_smem, const void* src) {
    uint32_t d = (uint32_t)__cvta_generic_to_shared(dst_smem);
    asm volatile("cp.async.cg.shared.global [%0], [%1], 16;" :: "r"(d), "l"(src));
}
#define CP_COMMIT() asm volatile("cp.async.commit_group;")
#define CP_WAIT0()  asm volatile("cp.async.wait_group 0;")

// ---------------------------------------------------------------------------
// GEMM (R11/R13/R14 verbatim, proven)
// ---------------------------------------------------------------------------
#define APAD 20
#define WPAD 136

__global__ void __launch_bounds__(256) gemm_xz_kernel(
    const float* __restrict__ Aext, const float* __restrict__ W,
    const float* __restrict__ bias, int layer0)
{
    __shared__ __align__(16) float As[2][128][APAD];
    __shared__ __align__(16) float Ws[2][16][WPAD];

    const int tid = threadIdx.x;
    const int bm = blockIdx.y * 128;
    const int bn = blockIdx.x * 128;

    const int wid = tid >> 5;
    const int lane = tid & 31;
    const int wm = wid >> 2;
    const int wn = wid & 3;
    const int gid = lane >> 2;
    const int tig = lane & 3;

    const int aRow = tid >> 1;
    const int aOff = (tid & 1) << 3;
    const float* aptr;
    {
        const int m = bm + aRow;
        if (layer0) aptr = Aext + ((size_t)(m & 63) * Tt + (m >> 6)) * Dd;
        else        aptr = g_hs0 + (size_t)m * Hh;
    }
    const int wRow = tid >> 4;
    const int wOff = (tid & 15) << 3;
    const float* wptr = W + (size_t)wRow * G4 + bn + wOff;

    cp16(&As[0][aRow][aOff],     aptr + aOff);
    cp16(&As[0][aRow][aOff + 4], aptr + aOff + 4);
    cp16(&Ws[0][wRow][wOff],     wptr);
    cp16(&Ws[0][wRow][wOff + 4], wptr + 4);
    CP_COMMIT();

    float acc[4][4][4];
#pragma unroll
    for (int i = 0; i < 4; i++)
#pragma unroll
        for (int j = 0; j < 4; j++)
#pragma unroll
            for (int q = 0; q < 4; q++) acc[i][j][q] = 0.0f;

    for (int k0 = 0; k0 < 1024; k0 += 16) {
        CP_WAIT0();
        __syncthreads();
        const int buf = (k0 >> 4) & 1;
        if (k0 + 16 < 1024) {
            const int nb = buf ^ 1;
            const float* an = aptr + k0 + 16;
            const float* wn_ = wptr + (size_t)(k0 + 16) * G4;
            cp16(&As[nb][aRow][aOff],     an + aOff);
            cp16(&As[nb][aRow][aOff + 4], an + aOff + 4);
            cp16(&Ws[nb][wRow][wOff],     wn_);
            cp16(&Ws[nb][wRow][wOff + 4], wn_ + 4);
            CP_COMMIT();
        }
#pragma unroll
        for (int s = 0; s < 2; s++) {
            const int ks = s * 8;
            uint32_t a_hi[4][4], a_lo[4][4], b_hi[4][2], b_lo[4][2];
#pragma unroll
            for (int mt = 0; mt < 4; mt++) {
                const int m = wm * 64 + mt * 16 + gid;
                split_tf32(As[buf][m][ks + tig],         a_hi[mt][0], a_lo[mt][0]);
                split_tf32(As[buf][m + 8][ks + tig],     a_hi[mt][1], a_lo[mt][1]);
                split_tf32(As[buf][m][ks + tig + 4],     a_hi[mt][2], a_lo[mt][2]);
                split_tf32(As[buf][m + 8][ks + tig + 4], a_hi[mt][3], a_lo[mt][3]);
            }
#pragma unroll
            for (int nt = 0; nt < 4; nt++) {
                const int n = wn * 32 + nt * 8 + gid;
                split_tf32(Ws[buf][ks + tig][n],     b_hi[nt][0], b_lo[nt][0]);
                split_tf32(Ws[buf][ks + tig + 4][n], b_hi[nt][1], b_lo[nt][1]);
            }
#pragma unroll
            for (int mt = 0; mt < 4; mt++)
#pragma unroll
                for (int nt = 0; nt < 4; nt++) {
                    mma_tf32(acc[mt][nt], a_hi[mt], b_hi[nt]);
                    mma_tf32(acc[mt][nt], a_hi[mt], b_lo[nt]);
                    mma_tf32(acc[mt][nt], a_lo[mt], b_hi[nt]);
                }
        }
    }

#pragma unroll
    for (int mt = 0; mt < 4; mt++) {
#pragma unroll
        for (int nt = 0; nt < 4; nt++) {
            const int gn = bn + wn * 32 + nt * 8 + 2 * tig;
            const float b0v = bias[gn];
            const float b1v = bias[gn + 1];
            const int r0 = bm + wm * 64 + mt * 16 + gid;
            float* p0 = g_xz + (size_t)r0 * G4 + gn;
            float* p1 = g_xz + (size_t)(r0 + 8) * G4 + gn;
            p0[0] = acc[mt][nt][0] + b0v;
            p0[1] = acc[mt][nt][1] + b1v;
            p1[0] = acc[mt][nt][2] + b0v;
            p1[1] = acc[mt][nt][3] + b1v;
        }
    }
}

// ---------------------------------------------------------------------------
// U prep (R14 verbatim, proven)
// ---------------------------------------------------------------------------
__global__ void __launch_bounds__(256) prep_upk_kernel(const float* __restrict__ U) {
    const int i = blockIdx.x * 256 + threadIdx.x;   // 0..1048575
    const int lane = i & 31;
    const int nt   = (i >> 5) & 3;
    const int ks   = (i >> 7) & 31;
    const int kw   = (i >> 12) & 1;
    const int blk  = i >> 13;
    const int tig = lane & 3;
    const int gid = lane >> 2;
    const int kA = kw * 512 + ks * 16 + 2 * tig;
    const int col = nt * Hh + blk * 8 + gid;

    const float u00 = U[(size_t)kA * G4 + col];
    const float u01 = U[(size_t)(kA + 1) * G4 + col];
    const float u10 = U[(size_t)(kA + 8) * G4 + col];
    const float u11 = U[(size_t)(kA + 9) * G4 + col];

    __nv_bfloat162 h0 = __floats2bfloat162_rn(u00, u01);
    __nv_bfloat162 h1 = __floats2bfloat162_rn(u10, u11);
    __nv_bfloat162 l0 = __floats2bfloat162_rn(u00 - __bfloat162float(h0.x),
                                              u01 - __bfloat162float(h0.y));
    __nv_bfloat162 l1 = __floats2bfloat162_rn(u10 - __bfloat162float(h1.x),
                                              u11 - __bfloat162float(h1.y));
    uint4 v;
    v.x = b2bits(h0); v.y = b2bits(h1); v.z = b2bits(l0); v.w = b2bits(l1);
    g_Upk[i] = v;
}

// ---------------------------------------------------------------------------
// Persistent bf16 scan v2: U smem-resident; h A-frags loaded DIRECTLY from
// global (ld.global.cg) into registers, software double-buffered.
// No per-chunk cp.async waits, no per-chunk __syncthreads.
// Math/accumulation order identical to R14 -> rel_err must be 1.012518e-05.
// ---------------------------------------------------------------------------
#define SCAN_SMEM (131072 + 8192)   // U + reduction = 139264 B

// load one chunk's A-frag words (32 per thread) into dst[sk][8]
__device__ __forceinline__ void load_hchunk(
    uint32_t dst[4][8], int par, int kw, int c, int tig, int b0, int b1)
{
    const uint32_t* Hhi = &g_hP[par][0][0][0];
    const uint32_t* Hlo = &g_hP[par][1][0][0];
#pragma unroll
    for (int sk = 0; sk < 4; sk++) {
        const int r0 = kw * 256 + c * 32 + sk * 8 + tig;
        const int r1 = r0 + 4;
        dst[sk][0] = ldcg_u32(Hhi + r0 * 64 + b0);
        dst[sk][1] = ldcg_u32(Hhi + r0 * 64 + b1);
        dst[sk][2] = ldcg_u32(Hhi + r1 * 64 + b0);
        dst[sk][3] = ldcg_u32(Hhi + r1 * 64 + b1);
        dst[sk][4] = ldcg_u32(Hlo + r0 * 64 + b0);
        dst[sk][5] = ldcg_u32(Hlo + r0 * 64 + b1);
        dst[sk][6] = ldcg_u32(Hlo + r1 * 64 + b0);
        dst[sk][7] = ldcg_u32(Hlo + r1 * 64 + b1);
    }
}

__global__ void __launch_bounds__(256, 1) lstm_scan_tc(
    const int* __restrict__ lengths, float* __restrict__ out_base,
    float* __restrict__ out_tail, int layer)
{
    extern __shared__ uint8_t smraw[];
    uint4* usm = (uint4*)smraw;                          // [kw][ks32][nt4][lane32]
    float* red = (float*)(smraw + 131072);               // [16][128]

    const int tid = threadIdx.x;
    const int blk = blockIdx.x;
    const int wid = tid >> 5;
    const int lane = tid & 31;
    const int gid = lane >> 2;
    const int tig = lane & 3;
    const int kw = tid >> 7;
    const int gtid = tid & 127;
    const int w4 = wid & 3;
    const int j0 = blk * 8;
    unsigned sense = 0;

    // U resident fill: 64 KB per group (once)
    {
        const uint4* usrc = g_Upk + ((size_t)(blk * 2 + kw)) * 4096 + gtid * 32;
        uint4* udst = usm + kw * 4096 + gtid * 32;
#pragma unroll
        for (int q = 0; q < 32; q++) cp16(udst + q, usrc + q);
    }
    CP_COMMIT();

    // zero initial h (parity 0, hi+lo)
    {
        uint2* p = reinterpret_cast<uint2*>(&g_hP[0][0][0][0]);
        __stcg(p + (blk * 256 + tid), make_uint2(0u, 0u));
    }

    const int b0 = w4 * 16 + gid;
    const int b1 = b0 + 8;
    const int jA = j0 + 2 * tig;
    const int k2g = blk * 4 + tig;
    int len0 = 0, len1 = 0;
    if (kw == 0) { len0 = lengths[b0]; len1 = lengths[b1]; }

    float cb[4] = {0.f, 0.f, 0.f, 0.f};
    float hp[4] = {0.f, 0.f, 0.f, 0.f};

    grid_sync(sense, gridDim.x);   // sync #1 (h0 zeros + all blocks ready)
    CP_WAIT0();                    // own U stores complete
    __syncthreads();               // U visible block-wide

    const uint4* Ug = usm + kw * 4096;

    for (int t = 0; t < Tt; t++) {
        const float* xz = g_xz + (size_t)t * (Bz * G4);
        float2 xv[4][2];
        if (kw == 0) {
#pragma unroll
            for (int g = 0; g < 4; g++) {
                xv[g][0] = *(const float2*)(xz + (size_t)b0 * G4 + g * Hh + jA);
                xv[g][1] = *(const float2*)(xz + (size_t)b1 * G4 + g * Hh + jA);
            }
        }
        if (t) grid_sync(sense, gridDim.x);
        const int par = t & 1;

        float accA[4][4], accB[4][4], accC[4][4];
#pragma unroll
        for (int nt = 0; nt < 4; nt++)
#pragma unroll
            for (int q = 0; q < 4; q++) {
                accA[nt][q] = 0.f; accB[nt][q] = 0.f; accC[nt][q] = 0.f;
            }

        uint32_t aw[2][4][8];
        load_hchunk(aw[0], par, kw, 0, tig, b0, b1);

        for (int c = 0; c < 8; c++) {
            const int cur = c & 1;
            if (c < 7) load_hchunk(aw[cur ^ 1], par, kw, c + 1, tig, b0, b1);
#pragma unroll
            for (int sk = 0; sk < 4; sk++) {
                const uint32_t* ah = &aw[cur][sk][0];
                const uint32_t* al = &aw[cur][sk][4];
                const int ksg = c * 4 + sk;
#pragma unroll
                for (int nt = 0; nt < 4; nt++) {
                    const uint4 v = Ug[(ksg * 4 + nt) * 32 + lane];
                    uint32_t bh[2], bl[2];
                    bh[0] = v.x; bh[1] = v.y; bl[0] = v.z; bl[1] = v.w;
                    mma_bf16(accA[nt], ah, bh);
                    mma_bf16(accB[nt], ah, bl);
                    mma_bf16(accC[nt], al, bh);
                }
            }
        }
        __syncthreads();

        if (kw == 1) {
#pragma unroll
            for (int nt = 0; nt < 4; nt++)
#pragma unroll
                for (int q = 0; q < 4; q++)
                    red[(nt * 4 + q) * 128 + w4 * 32 + lane] =
                        accA[nt][q] + accB[nt][q] + accC[nt][q];
        }
        __syncthreads();

        if (kw == 0) {
            float h2a[4];
#pragma unroll
            for (int q = 0; q < 4; q++) {
                const int r = q >> 1;
                const int ccsel = q & 1;
                const float zi = accA[0][q] + accB[0][q] + accC[0][q]
                               + red[(0 * 4 + q) * 128 + w4 * 32 + lane]
                               + (ccsel ? xv[0][r].y : xv[0][r].x);
                const float zf = accA[1][q] + accB[1][q] + accC[1][q]
                               + red[(1 * 4 + q) * 128 + w4 * 32 + lane]
                               + (ccsel ? xv[1][r].y : xv[1][r].x);
                const float zg = accA[2][q] + accB[2][q] + accC[2][q]
                               + red[(2 * 4 + q) * 128 + w4 * 32 + lane]
                               + (ccsel ? xv[2][r].y : xv[2][r].x);
                const float zo = accA[3][q] + accB[3][q] + accC[3][q]
                               + red[(3 * 4 + q) * 128 + w4 * 32 + lane]
                               + (ccsel ? xv[3][r].y : xv[3][r].x);

                const float ig = 1.0f / (1.0f + __expf(-zi));
                const float fg = 1.0f / (1.0f + __expf(-zf));
                const float gg = tanhf(zg);
                const float og = 1.0f / (1.0f + __expf(-zo));

                const float cn = fg * cb[q] + ig * gg;
                const float hn = og * tanhf(cn);

                const bool msk = t < (r ? len1 : len0);
                const float h2 = msk ? hn : hp[q];
                const float c2 = msk ? cn : cb[q];
                hp[q] = h2; cb[q] = c2;
                h2a[q] = h2;

                const int b = r ? b1 : b0;
                const int j = jA + ccsel;
                if (layer == 0) {
                    g_hs0[(size_t)t * (Bz * Hh) + (size_t)b * Hh + j] = h2;
                } else {
                    out_base[(size_t)b * ((size_t)Tt * Hh) + (size_t)t * Hh + j] = h2;
                }
            }
            {
                __nv_bfloat162 vh = __floats2bfloat162_rn(h2a[0], h2a[1]);
                __nv_bfloat162 vl = __floats2bfloat162_rn(
                    h2a[0] - __bfloat162float(vh.x), h2a[1] - __bfloat162float(vh.y));
                __stcg(&g_hP[par ^ 1][0][k2g][b0], b2bits(vh));
                __stcg(&g_hP[par ^ 1][1][k2g][b0], b2bits(vl));
            }
            {
                __nv_bfloat162 vh = __floats2bfloat162_rn(h2a[2], h2a[3]);
                __nv_bfloat162 vl = __floats2bfloat162_rn(
                    h2a[2] - __bfloat162float(vh.x), h2a[3] - __bfloat162float(vh.y));
                __stcg(&g_hP[par ^ 1][0][k2g][b1], b2bits(vh));
                __stcg(&g_hP[par ^ 1][1][k2g][b1], b2bits(vl));
            }
        }
    }

    if (layer && kw == 0) {
#pragma unroll
        for (int q = 0; q < 4; q++) {
            const int b = (q >> 1) ? b1 : b0;
            const int j = jA + (q & 1);
            out_tail[(size_t)b * Hh + j] = hp[q];
            out_tail[(size_t)Bz * Hh + (size_t)b * Hh + j] = cb[q];
        }
    }
}

extern "C" void kernel_launch(void* const* d_in, const int* in_sizes, int n_in,
                              void* d_out, int out_size) {
    (void)in_sizes; (void)n_in; (void)out_size;
    const float* x  = (const float*)d_in[0];
    const int* lens = (const int*)d_in[1];
    const float* W0 = (const float*)d_in[2];
    const float* U0 = (const float*)d_in[3];
    const float* b0 = (const float*)d_in[4];
    const float* W1 = (const float*)d_in[5];
    const float* U1 = (const float*)d_in[6];
    const float* b1 = (const float*)d_in[7];
    float* out = (float*)d_out;

    cudaFuncSetAttribute(lstm_scan_tc,
                         cudaFuncAttributeMaxDynamicSharedMemorySize, SCAN_SMEM);

    const dim3 ggrid(G4 / 128, (Tt * Bz) / 128);

    gemm_xz_kernel<<<ggrid, 256>>>(x, W0, b0, 1);
    prep_upk_kernel<<<4096, 256>>>(U0);
    lstm_scan_tc<<<128, 256, SCAN_SMEM>>>(lens, nullptr, nullptr, 0);

    gemm_xz_kernel<<<ggrid, 256>>>(nullptr, W1, b1, 0);
    prep_upk_kernel<<<4096, 256>>>(U1);
    float* tail = out + (size_t)Bz * Tt * Hh;
    lstm_scan_tc<<<128, 256, SCAN_SMEM>>>(lens, out, tail, 1);
}